// round 8
// baseline (speedup 1.0000x reference)
#include <cuda_runtime.h>

#define N       4096
#define THREADS 128
#define PAD(i)  ((i) + ((i) >> 5))
#define SMW     (4096 + 128)

// Sign bitmask: bit e of g_smask[e>>5] = (s[e] < 0). 128 words, built per call.
__device__ unsigned g_smask[N / 32];

__global__ void pack_signs(const float* __restrict__ s)
{
    int i = blockIdx.x * blockDim.x + threadIdx.x;
    unsigned b = __ballot_sync(0xffffffffu, __float_as_int(s[i]) < 0);
    if ((threadIdx.x & 31) == 0) g_smask[i >> 5] = b;
}

__global__ __launch_bounds__(THREADS, 12)   // cap regs ~42 -> 48 warps/SM
void fwht_kernel(const float* __restrict__ x,
                 float* __restrict__ out)
{
    __shared__ float sm[SMW];

    const int row  = blockIdx.x;
    const int t    = threadIdx.x;   // 0..127
    const int lane = t & 31;
    const int w    = t >> 5;        // 0..3

    // ---- load 32 contiguous elements ----
    // initial layout: i[4:0]=reg, i[9:5]=lane, i[11:10]=w
    float v[32];
    const float4* xr = reinterpret_cast<const float4*>(x + (size_t)row * N + t * 32);
    #pragma unroll
    for (int j = 0; j < 8; j++) {
        float4 a = xr[j];
        v[4*j+0] = a.x; v[4*j+1] = a.y; v[4*j+2] = a.z; v[4*j+3] = a.w;
    }

    // ---- apply signs via bitmask XOR (one word per thread: elements t*32+k) ----
    {
        const unsigned m = g_smask[t];
        #pragma unroll
        for (int k = 0; k < 32; k++)
            v[k] = __int_as_float(__float_as_int(v[k]) ^
                                  (int)((m << (31 - k)) & 0x80000000u));
    }

    // ---- stage 1: FWHT over reg bits i[4:0], 5 levels ----
    #pragma unroll
    for (int m = 1; m < 32; m <<= 1) {
        #pragma unroll
        for (int r = 0; r < 32; r++) {
            if ((r & m) == 0) {
                float a = v[r], b = v[r | m];
                v[r]     = a + b;
                v[r | m] = a - b;
            }
        }
    }

    // ---- stage 2: 2 half-exchange shuffle levels (i5 then i6) ----
    // Each level swaps roles of reg bit 4 and the lane bit.
    // After: regs = {i0,i1,i2,i3, i6}, lane = {i4,i5,i7,i8,i9}, w = i[11:10].
    #pragma unroll
    for (int mm = 1; mm < 4; mm <<= 1) {
        const bool  lo  = (lane & mm) == 0;
        const float sgn = lo ? 1.0f : -1.0f;
        #pragma unroll
        for (int r = 0; r < 16; r++) {
            float keep = lo ? v[r]      : v[r + 16];
            float send = lo ? v[r + 16] : v[r];
            float recv = __shfl_xor_sync(0xffffffffu, send, mm);
            v[r]      = keep + recv;
            v[r + 16] = (keep - recv) * sgn;
        }
    }

    // ---- transpose ----
    // smem address map (weights chosen conflict-free for BOTH patterns):
    // a = i4 + i5<<1 + i7<<2 + i8<<3 + i9<<4 + i6<<5 + i0<<6 + i1<<7 + i2<<8
    //   + i3<<9 + i10<<10 + i11<<11
    // write: lane bits {i4,i5,i7,i8,i9} -> a[4:0]  => bank = lane + const
    const int wb = lane | (w << 10);
    #pragma unroll
    for (int r = 0; r < 32; r++) {
        int a = wb | ((r >> 4) << 5) | ((r & 15) << 6);   // r4=i6, r[3:0]=i[3:0]
        sm[PAD(a)] = v[r];
    }
    __syncthreads();

    // read: thread lane' = i[4:0], w' = {i5,i6}; regs rp = {i7,i8,i9,i10,i11}
    // a = lane'4 + w'0<<1 + rp0<<2 + rp1<<3 + rp2<<4 + w'1<<5 + lane'0<<6
    //   + lane'1<<7 + lane'2<<8 + lane'3<<9 + rp3<<10 + rp4<<11
    // varying lane bank weights: {1,2,4,8,16} -> conflict-free
    const int rb = (lane >> 4) | ((w & 1) << 1) | ((w >> 1) << 5) | ((lane & 15) << 6);
    float u[32];
    #pragma unroll
    for (int rp = 0; rp < 32; rp++) {
        int a = rb | ((rp & 7) << 2) | ((rp >> 3) << 10);
        u[rp] = sm[PAD(a)];
    }

    // ---- stage 3: FWHT over remaining bits i[11:7] = rp[4:0], 5 levels ----
    #pragma unroll
    for (int m = 1; m < 32; m <<= 1) {
        #pragma unroll
        for (int rp = 0; rp < 32; rp++) {
            if ((rp & m) == 0) {
                float a = u[rp], b = u[rp | m];
                u[rp]     = a + b;
                u[rp | m] = a - b;
            }
        }
    }

    // ---- scaled, fully-coalesced store (32 contiguous floats per warp per rp) ----
    const float scale = 0.015625f;   // 1/sqrt(4096)
    float* orow = out + (size_t)row * N;
    const int ob = (w << 5) | lane;  // o = lane | w<<5 | rp<<7
    #pragma unroll
    for (int rp = 0; rp < 32; rp++)
        orow[ob | (rp << 7)] = u[rp] * scale;
}

extern "C" void kernel_launch(void* const* d_in, const int* in_sizes, int n_in,
                              void* d_out, int out_size)
{
    const float* x = (const float*)d_in[0];
    const float* s = (const float*)d_in[1];
    float* out     = (float*)d_out;

    pack_signs<<<N / 1024, 1024>>>(s);

    const int rows = in_sizes[0] / N;   // 16384
    fwht_kernel<<<rows, THREADS>>>(x, out);
}

// round 9
// speedup vs baseline: 1.3426x; 1.3426x over previous
#include <cuda_runtime.h>
#include <cuda_fp16.h>

#define N       4096
#define THREADS 256
#define PAD(i)  ((i) + ((i) >> 5))
#define SMW     (2048 + 64)    // half2 words + padding

// Sign bitmask: bit e of g_smask[e>>5] = (s[e] < 0).
__device__ unsigned g_smask[N / 32];

__global__ void pack_signs(const float* __restrict__ s)
{
    int i = blockIdx.x * blockDim.x + threadIdx.x;
    unsigned b = __ballot_sync(0xffffffffu, __float_as_int(s[i]) < 0);
    if ((threadIdx.x & 31) == 0) g_smask[i >> 5] = b;
}

__global__ __launch_bounds__(THREADS)
void fwht_kernel(const float* __restrict__ x,
                 float* __restrict__ out)
{
    __shared__ __half2 sm[SMW];

    const int row  = blockIdx.x;
    const int t    = threadIdx.x;
    const int lane = t & 31;
    const int w    = t >> 5;

    // ---- load 16 contiguous elements: i[3:0]=reg, i[8:4]=lane, i[11:9]=w ----
    float v[16];
    const float4* xr = reinterpret_cast<const float4*>(x + (size_t)row * N + t * 16);
    #pragma unroll
    for (int j = 0; j < 4; j++) {
        float4 a = xr[j];
        v[4*j+0] = a.x; v[4*j+1] = a.y; v[4*j+2] = a.z; v[4*j+3] = a.w;
    }

    // ---- signs via bitmask XOR ----
    {
        const unsigned m = g_smask[t >> 1] >> ((t & 1) << 4);
        #pragma unroll
        for (int k = 0; k < 16; k++)
            v[k] = __int_as_float(__float_as_int(v[k]) ^
                                  (int)((m << (31 - k)) & 0x80000000u));
    }

    // ---- stage 1 (fp32): butterfly reg bits i1,i2,i3 (i0 rides) ----
    #pragma unroll
    for (int m = 2; m < 16; m <<= 1) {
        #pragma unroll
        for (int r = 0; r < 16; r++) {
            if ((r & m) == 0) {
                float a = v[r], b = v[r | m];
                v[r]     = a + b;
                v[r | m] = a - b;
            }
        }
    }

    // ---- pack pairs along i0: h[j] = (v[2j], v[2j+1]); j bits = (i1,i2,i3) ----
    __half2 h[8];
    #pragma unroll
    for (int j = 0; j < 8; j++)
        h[j] = __floats2half2_rn(v[2*j], v[2*j+1]);

    // ---- 5 packed half-exchange levels over lane bits i4..i8 ----
    // split on j2 (reg3-chain); after all levels lanes=(i3,i4,i5,i6,i7), j2=i8
    const __half2 POS = __floats2half2_rn( 1.0f,  1.0f);
    const __half2 NEG = __floats2half2_rn(-1.0f, -1.0f);
    #pragma unroll
    for (int mm = 1; mm < 32; mm <<= 1) {
        const bool    lo   = (lane & mm) == 0;
        const __half2 sgn2 = lo ? POS : NEG;
        #pragma unroll
        for (int j = 0; j < 4; j++) {
            __half2 keep = lo ? h[j]     : h[j + 4];
            __half2 send = lo ? h[j + 4] : h[j];
            unsigned su  = *reinterpret_cast<unsigned*>(&send);
            unsigned ru  = __shfl_xor_sync(0xffffffffu, su, mm);
            __half2 recv = *reinterpret_cast<__half2*>(&ru);
            h[j]     = __hadd2(keep, recv);
            h[j + 4] = __hmul2(__hsub2(keep, recv), sgn2);
        }
    }

    // ---- transpose write (half2 words) ----
    // word addr a = i6 +2*i7 +4*i3 +8*i4 +16*i5 +32*i1 +64*i2 +128*i8 +256*i9 +512*i10 +1024*i11
    // writer: lanes (L0..L4)=(i3,i4,i5,i6,i7) -> bank weights {4,8,16,1,2}: conflict-free
    const int a_wl = ((lane >> 3) & 1) | ((lane >> 4) << 1) | ((lane & 1) << 2)
                   | (((lane >> 1) & 1) << 3) | (((lane >> 2) & 1) << 4);
    #pragma unroll
    for (int j = 0; j < 8; j++)
        sm[PAD(a_wl | (j << 5) | (w << 8))] = h[j];
    __syncthreads();

    // ---- transpose read: lane'=(i1..i5), w'=(i6,i7,i8), words vary k=(i9,i10,i11) ----
    // bank weights over lane' = {1,2,4,8,16}: conflict-free
    const int a_rd = (w & 1) | (((w >> 1) & 1) << 1) | (((lane >> 2) & 1) << 2)
                   | (((lane >> 3) & 1) << 3) | ((lane >> 4) << 4)
                   | ((lane & 1) << 5) | (((lane >> 1) & 1) << 6) | ((w >> 2) << 7);
    float u[16];
    #pragma unroll
    for (int k = 0; k < 8; k++) {
        float2 f = __half22float2(sm[PAD(a_rd | (k << 8))]);
        u[2*k]   = f.x;     // i0 = 0
        u[2*k+1] = f.y;     // i0 = 1
    }

    // ---- stage 3 (fp32): 4 levels over u bits {i0, i9, i10, i11} ----
    #pragma unroll
    for (int m = 1; m < 16; m <<= 1) {
        #pragma unroll
        for (int r = 0; r < 16; r++) {
            if ((r & m) == 0) {
                float a = u[r], b = u[r | m];
                u[r]     = a + b;
                u[r | m] = a - b;
            }
        }
    }

    // ---- scaled store: o = (k<<9)|(w'<<6)|(lane'<<1)|i0 -> float2, coalesced ----
    const float scale = 0.015625f;   // 1/sqrt(4096)
    float* orow = out + (size_t)row * N;
    const int ob = (w << 6) | (lane << 1);
    #pragma unroll
    for (int k = 0; k < 8; k++) {
        float2 f2 = make_float2(u[2*k] * scale, u[2*k+1] * scale);
        *reinterpret_cast<float2*>(orow + (ob | (k << 9))) = f2;
    }
}

extern "C" void kernel_launch(void* const* d_in, const int* in_sizes, int n_in,
                              void* d_out, int out_size)
{
    const float* x = (const float*)d_in[0];
    const float* s = (const float*)d_in[1];
    float* out     = (float*)d_out;

    pack_signs<<<N / 1024, 1024>>>(s);

    const int rows = in_sizes[0] / N;   // 16384
    fwht_kernel<<<rows, THREADS>>>(x, out);
}

// round 11
// speedup vs baseline: 1.6981x; 1.2648x over previous
#include <cuda_runtime.h>
#include <cuda_fp16.h>

#define N       4096
#define THREADS 256
#define PAD(i)  ((i) + ((i) >> 5))
#define SMW     (2048 + 64)    // half2 words + padding

// Sign bitmask: bit e of g_smask[e>>5] = (s[e] < 0).
__device__ unsigned g_smask[N / 32];

__global__ void pack_signs(const float* __restrict__ s)
{
    int i = blockIdx.x * blockDim.x + threadIdx.x;
    unsigned b = __ballot_sync(0xffffffffu, __float_as_int(s[i]) < 0);
    if ((threadIdx.x & 31) == 0) g_smask[i >> 5] = b;
}

__global__ __launch_bounds__(THREADS)
void fwht_kernel(const float* __restrict__ x,
                 float* __restrict__ out)
{
    __shared__ __half2 sm[SMW];

    const int row  = blockIdx.x;
    const int t    = threadIdx.x;
    const int lane = t & 31;      // = i[8:4]
    const int w    = t >> 5;      // = i[11:9]

    // ---- load 16 contiguous elements: i[3:0]=reg, i[8:4]=lane, i[11:9]=w ----
    float v[16];
    const float4* xr = reinterpret_cast<const float4*>(x + (size_t)row * N + t * 16);
    #pragma unroll
    for (int j = 0; j < 4; j++) {
        float4 a = xr[j];
        v[4*j+0] = a.x; v[4*j+1] = a.y; v[4*j+2] = a.z; v[4*j+3] = a.w;
    }

    // ---- signs via bitmask XOR ----
    {
        const unsigned m = g_smask[t >> 1] >> ((t & 1) << 4);
        #pragma unroll
        for (int k = 0; k < 16; k++)
            v[k] = __int_as_float(__float_as_int(v[k]) ^
                                  (int)((m << (31 - k)) & 0x80000000u));
    }

    // ---- stage 1 (fp32): butterfly reg bits i1,i2,i3 (i0 rides along) ----
    #pragma unroll
    for (int m = 2; m < 16; m <<= 1) {
        #pragma unroll
        for (int r = 0; r < 16; r++) {
            if ((r & m) == 0) {
                float a = v[r], b = v[r | m];
                v[r]     = a + b;
                v[r | m] = a - b;
            }
        }
    }

    // ---- pack pairs along i0: h[j] = (v[2j], v[2j+1]); j bits = (i1,i2,i3) ----
    __half2 h[8];
    #pragma unroll
    for (int j = 0; j < 8; j++)
        h[j] = __floats2half2_rn(v[2*j], v[2*j+1]);

    // ---- stage 2: 5 FULL-exchange packed levels over lane bits i4..i8 ----
    // h[j] = sgn*h[j] + shfl_xor(h[j])  (HFMA2; no selects, no bit migration)
    const __half2 POS = __floats2half2_rn( 1.0f,  1.0f);
    const __half2 NEG = __floats2half2_rn(-1.0f, -1.0f);
    #pragma unroll
    for (int mm = 1; mm < 32; mm <<= 1) {
        const __half2 sgn2 = (lane & mm) ? NEG : POS;
        #pragma unroll
        for (int j = 0; j < 8; j++) {
            unsigned su = *reinterpret_cast<unsigned*>(&h[j]);
            unsigned ru = __shfl_xor_sync(0xffffffffu, su, mm);
            __half2 recv = *reinterpret_cast<__half2*>(&ru);
            h[j] = __hfma2(sgn2, h[j], recv);
        }
    }

    // ---- transpose (half2 words) ----
    // word addr: a = i4 +2*i5 +4*i1 +8*i2 +16*i3 +32*i9 +64*i10 +128*i6 +256*i7 +512*i8 +1024*i11
    // write-varying lane bits {i4..i8} -> bank weights {1,2,4,8,16}: conflict-free
    const int wbase = (lane & 3)
                    | (((lane >> 2) & 1) << 7)
                    | (((lane >> 3) & 1) << 8)
                    | ((lane >> 4) << 9)
                    | ((w & 3) << 5)
                    | ((w >> 2) << 10);
    #pragma unroll
    for (int j = 0; j < 8; j++)
        sm[PAD(wbase | (j << 2))] = h[j];
    __syncthreads();

    // ---- read: lane' = (i1..i5), w' = (i6,i7,i8); vary k = (i9,i10,i11) ----
    // read-varying lane bits weights {4,8,16,1,2}: conflict-free
    const int rbase = (lane >> 3) | ((lane & 7) << 2) | (w << 7);
    float u[16];
    #pragma unroll
    for (int k = 0; k < 8; k++) {
        int a = rbase | ((k & 3) << 5) | ((k >> 2) << 10);
        float2 f = __half22float2(sm[PAD(a)]);
        u[2*k]   = f.x;     // i0 = 0
        u[2*k+1] = f.y;     // i0 = 1
    }

    // ---- stage 3 (fp32): 4 levels over bits {i0, i9, i10, i11} ----
    #pragma unroll
    for (int m = 1; m < 16; m <<= 1) {
        #pragma unroll
        for (int r = 0; r < 16; r++) {
            if ((r & m) == 0) {
                float a = u[r], b = u[r | m];
                u[r]     = a + b;
                u[r | m] = a - b;
            }
        }
    }

    // ---- scaled store: o = (k<<9)|(w'<<6)|(lane'<<1)|i0  -> float2, coalesced ----
    const float scale = 0.015625f;   // 1/sqrt(4096)
    float* orow = out + (size_t)row * N;
    const int ob = (w << 6) | (lane << 1);
    #pragma unroll
    for (int k = 0; k < 8; k++) {
        float2 f2 = make_float2(u[2*k] * scale, u[2*k+1] * scale);
        *reinterpret_cast<float2*>(orow + (ob | (k << 9))) = f2;
    }
}

extern "C" void kernel_launch(void* const* d_in, const int* in_sizes, int n_in,
                              void* d_out, int out_size)
{
    const float* x = (const float*)d_in[0];
    const float* s = (const float*)d_in[1];
    float* out     = (float*)d_out;

    pack_signs<<<N / 1024, 1024>>>(s);

    const int rows = in_sizes[0] / N;   // 16384
    fwht_kernel<<<rows, THREADS>>>(x, out);
}

// round 12
// speedup vs baseline: 1.7242x; 1.0154x over previous
#include <cuda_runtime.h>
#include <cuda_fp16.h>

#define N       4096
#define THREADS 256
#define PAD(i)  ((i) + ((i) >> 5))

// Sign bitmask: bit e of g_smask[e>>5] = (s[e] < 0).
__device__ unsigned g_smask[N / 32];

__global__ void pack_signs(const float* __restrict__ s)
{
    int i = blockIdx.x * blockDim.x + threadIdx.x;
    unsigned b = __ballot_sync(0xffffffffu, __float_as_int(s[i]) < 0);
    if ((threadIdx.x & 31) == 0) g_smask[i >> 5] = b;
}

__global__ __launch_bounds__(THREADS)
void fwht_kernel(const float* __restrict__ x,
                 float* __restrict__ out)
{
    // Buffer A: warp-local transpose (needs PAD). Buffer B: CTA transpose (bank=lane, no pad).
    __shared__ __half2 smA[2048 + 64];
    __shared__ __half2 smB[2048];

    const int row  = blockIdx.x;
    const int t    = threadIdx.x;
    const int lane = t & 31;      // = i[8:4] initially
    const int w    = t >> 5;      // = i[11:9] (fixed per thread throughout)

    // ---- load 16 contiguous elements: i[3:0]=reg, i[8:4]=lane, i[11:9]=w ----
    float v[16];
    const float4* xr = reinterpret_cast<const float4*>(x + (size_t)row * N + t * 16);
    #pragma unroll
    for (int j = 0; j < 4; j++) {
        float4 a = __ldcs(xr + j);
        v[4*j+0] = a.x; v[4*j+1] = a.y; v[4*j+2] = a.z; v[4*j+3] = a.w;
    }

    // ---- signs via bitmask XOR ----
    {
        const unsigned m = g_smask[t >> 1] >> ((t & 1) << 4);
        #pragma unroll
        for (int k = 0; k < 16; k++)
            v[k] = __int_as_float(__float_as_int(v[k]) ^
                                  (int)((m << (31 - k)) & 0x80000000u));
    }

    // ---- stage 1 (fp32): butterfly ALL reg bits i0,i1,i2,i3 (4 levels) ----
    #pragma unroll
    for (int m = 1; m < 16; m <<= 1) {
        #pragma unroll
        for (int r = 0; r < 16; r++) {
            if ((r & m) == 0) {
                float a = v[r], b = v[r | m];
                v[r]     = a + b;
                v[r | m] = a - b;
            }
        }
    }

    // ---- pack pairs along i0 (already transformed): h[j], j bits = (i1,i2,i3) ----
    __half2 h[8];
    #pragma unroll
    for (int j = 0; j < 8; j++)
        h[j] = __floats2half2_rn(v[2*j], v[2*j+1]);

    // ---- stage 2a: 2 full-exchange packed levels over lane bits i4, i5 ----
    const __half2 POS = __floats2half2_rn( 1.0f,  1.0f);
    const __half2 NEG = __floats2half2_rn(-1.0f, -1.0f);
    #pragma unroll
    for (int mm = 1; mm < 4; mm <<= 1) {
        const __half2 sgn2 = (lane & mm) ? NEG : POS;
        #pragma unroll
        for (int j = 0; j < 8; j++) {
            unsigned su = *reinterpret_cast<unsigned*>(&h[j]);
            unsigned ru = __shfl_xor_sync(0xffffffffu, su, mm);
            __half2 recv = *reinterpret_cast<__half2*>(&ru);
            h[j] = __hfma2(sgn2, h[j], recv);
        }
    }

    // ---- transpose 1 (WARP-LOCAL: warp w holds all i1..i8 for its fixed w) ----
    // word addr: a = i4 +2*i5 +4*i1 +8*i2 +16*i3 +32*w0 +64*w1 +128*i6 +256*i7 +512*i8 +1024*w2
    // write-varying lane bits {i4..i8} -> bank weights {1,2,4,8,16} (with PAD): conflict-free
    const int wb1 = (lane & 3)
                  | (((lane >> 2) & 1) << 7)
                  | (((lane >> 3) & 1) << 8)
                  | (((lane >> 4) & 1) << 9)
                  | ((w & 3) << 5)
                  | ((w >> 2) << 10);
    #pragma unroll
    for (int j = 0; j < 8; j++)
        smA[PAD(wb1 | (j << 2))] = h[j];
    __syncwarp();

    // read: lane -> (i1..i5), loop j' = (i6,i7,i8); lane bank weights {4,8,16,1,2}: conflict-free
    const int rb1 = ((lane >> 3) & 1)
                  | (((lane >> 4) & 1) << 1)
                  | ((lane & 1) << 2)
                  | (((lane >> 1) & 1) << 3)
                  | (((lane >> 2) & 1) << 4)
                  | ((w & 3) << 5)
                  | ((w >> 2) << 10);
    #pragma unroll
    for (int j = 0; j < 8; j++)
        h[j] = smA[PAD(rb1 | (j << 7))];

    // ---- stage 2b: packed fp16 butterfly over word bits j' = (i6,i7,i8), 3 levels ----
    #pragma unroll
    for (int m = 1; m < 8; m <<= 1) {
        #pragma unroll
        for (int j = 0; j < 8; j++) {
            if ((j & m) == 0) {
                __half2 a = h[j], b = h[j | m];
                h[j]     = __hadd2(a, b);
                h[j | m] = __hsub2(a, b);
            }
        }
    }

    // ---- transpose 2 (CTA-level): bring w bits (i9,i10,i11) into words ----
    // addr b = (i1..i5) + i6..i8<<5 (writer: j'; reader: its w) + i9..i11<<8
    // both write and read: bank = lane -> conflict-free, no padding
    const int b2w = lane | (w << 8);
    #pragma unroll
    for (int j = 0; j < 8; j++)
        smB[b2w | (j << 5)] = h[j];
    __syncthreads();

    const int b2r = lane | (w << 5);
    float u[16];
    #pragma unroll
    for (int k = 0; k < 8; k++) {
        float2 f = __half22float2(smB[b2r | (k << 8)]);
        u[2*k]   = f.x;     // i0 = 0
        u[2*k+1] = f.y;     // i0 = 1
    }

    // ---- stage 3 (fp32): butterfly k bits (i9,i10,i11) = u bits 1..3 (i0 done) ----
    #pragma unroll
    for (int m = 2; m < 16; m <<= 1) {
        #pragma unroll
        for (int r = 0; r < 16; r++) {
            if ((r & m) == 0) {
                float a = u[r], b = u[r | m];
                u[r]     = a + b;
                u[r | m] = a - b;
            }
        }
    }

    // ---- scaled streaming store: o = (k<<9)|(w<<6)|(lane<<1)|i0 -> float2, coalesced ----
    const float scale = 0.015625f;   // 1/sqrt(4096)
    float* orow = out + (size_t)row * N;
    const int ob = (w << 6) | (lane << 1);
    #pragma unroll
    for (int k = 0; k < 8; k++) {
        float2 f2 = make_float2(u[2*k] * scale, u[2*k+1] * scale);
        __stcs(reinterpret_cast<float2*>(orow + (ob | (k << 9))), f2);
    }
}

extern "C" void kernel_launch(void* const* d_in, const int* in_sizes, int n_in,
                              void* d_out, int out_size)
{
    const float* x = (const float*)d_in[0];
    const float* s = (const float*)d_in[1];
    float* out     = (float*)d_out;

    pack_signs<<<N / 1024, 1024>>>(s);

    const int rows = in_sizes[0] / N;   // 16384
    fwht_kernel<<<rows, THREADS>>>(x, out);
}